// round 1
// baseline (speedup 1.0000x reference)
#include <cuda_runtime.h>
#include <math.h>

#define NHEADS 8
#define DIMH   64
#define BATCH  4
#define NQ     2048
#define NC     2048
#define DQ     1024
#define DC     768
#define INNER  512   // NHEADS * DIMH

// Scratch (allocation-free rule: __device__ globals)
__device__ float g_Q [BATCH * NQ * INNER];
__device__ float g_K [BATCH * NC * INNER];
__device__ float g_V [BATCH * NC * INNER];
__device__ float g_AO[BATCH * NQ * INNER];

// ---------------------------------------------------------------------------
// SGEMM: C[M,N] = A[M,K] @ B[K,N] (+ bias[N]), 128x128 tile, BK=8, 256 threads
// All of M,N divisible by 128 and K divisible by 8 for every call site.
// ---------------------------------------------------------------------------
__global__ __launch_bounds__(256) void sgemm_kernel(
    const float* __restrict__ A, const float* __restrict__ Bm,
    const float* __restrict__ bias, float* __restrict__ C,
    int M, int N, int K)
{
    __shared__ float As[8][128];
    __shared__ float Bs[8][128];

    const int tid = threadIdx.x;
    const int bx = blockIdx.x, by = blockIdx.y;
    const int ty = tid >> 4, tx = tid & 15;

    const float* Ab = A + (size_t)by * 128 * K;
    const float* Bb = Bm + (size_t)bx * 128;

    float acc[8][8];
#pragma unroll
    for (int i = 0; i < 8; i++)
#pragma unroll
        for (int j = 0; j < 8; j++) acc[i][j] = 0.f;

    const int arow = tid >> 1;          // 0..127
    const int acol = (tid & 1) * 4;     // 0 or 4
    const int brow = tid >> 5;          // 0..7
    const int bcol = (tid & 31) * 4;    // 0..124

    for (int k0 = 0; k0 < K; k0 += 8) {
        float4 av = *(const float4*)(Ab + (size_t)arow * K + k0 + acol);
        float4 bv = *(const float4*)(Bb + (size_t)(k0 + brow) * N + bcol);
        __syncthreads();
        As[acol + 0][arow] = av.x;
        As[acol + 1][arow] = av.y;
        As[acol + 2][arow] = av.z;
        As[acol + 3][arow] = av.w;
        *(float4*)&Bs[brow][bcol] = bv;
        __syncthreads();
#pragma unroll
        for (int kk = 0; kk < 8; kk++) {
            float4 a0 = *(float4*)&As[kk][ty * 8];
            float4 a1 = *(float4*)&As[kk][ty * 8 + 4];
            float4 b0 = *(float4*)&Bs[kk][tx * 8];
            float4 b1 = *(float4*)&Bs[kk][tx * 8 + 4];
            float a[8] = {a0.x, a0.y, a0.z, a0.w, a1.x, a1.y, a1.z, a1.w};
            float b[8] = {b0.x, b0.y, b0.z, b0.w, b1.x, b1.y, b1.z, b1.w};
#pragma unroll
            for (int i = 0; i < 8; i++)
#pragma unroll
                for (int j = 0; j < 8; j++) acc[i][j] = fmaf(a[i], b[j], acc[i][j]);
        }
    }

    float badd[8] = {0, 0, 0, 0, 0, 0, 0, 0};
    if (bias) {
        const float* bp = bias + bx * 128 + tx * 8;
#pragma unroll
        for (int j = 0; j < 8; j++) badd[j] = bp[j];
    }
#pragma unroll
    for (int i = 0; i < 8; i++) {
        int row = by * 128 + ty * 8 + i;
        float* Cr = C + (size_t)row * N + bx * 128 + tx * 8;
        float4 c0 = make_float4(acc[i][0] + badd[0], acc[i][1] + badd[1],
                                acc[i][2] + badd[2], acc[i][3] + badd[3]);
        float4 c1 = make_float4(acc[i][4] + badd[4], acc[i][5] + badd[5],
                                acc[i][6] + badd[6], acc[i][7] + badd[7]);
        *(float4*)Cr = c0;
        *(float4*)(Cr + 4) = c1;
    }
}

// ---------------------------------------------------------------------------
// Flash attention, fp32. One block = 64 query rows for one (b, h).
// Q/K held d-major in smem (Qt[d][r], Kt[d][c]) so S-GEMM frags are LDS.128.
// S stored transposed (St[c][r]) so the P@V pass also uses LDS.128 frags.
// Online softmax, 4 lanes per row.
// ---------------------------------------------------------------------------
#define SPAD 68   // 64 + 4 pad: keeps float4 alignment, kills bank conflicts

__global__ __launch_bounds__(256) void flash_kernel(
    const float* __restrict__ Qg, const float* __restrict__ Kg,
    const float* __restrict__ Vg, float* __restrict__ Og)
{
    extern __shared__ float sm[];
    float* Qt = sm;                 // [64][SPAD]  Qt[d*SPAD + r]
    float* Kt = Qt + 64 * SPAD;     // [64][SPAD]  Kt[d*SPAD + c]
    float* Vs = Kt + 64 * SPAD;     // [64][SPAD]  Vs[kv*SPAD + d]
    float* St = Vs + 64 * SPAD;     // [64][SPAD]  St[c*SPAD + r]
    float* mrow = St + 64 * SPAD;   // [64]
    float* lrow = mrow + 64;        // [64]
    float* arow = lrow + 64;        // [64]

    const int tid = threadIdx.x;
    const int qt = blockIdx.x, h = blockIdx.y, b = blockIdx.z;
    const size_t qbase = ((size_t)b * NQ + (size_t)qt * 64) * INNER + h * DIMH;
    const size_t kbase = ((size_t)b * NC) * INNER + h * DIMH;

    // Load Q tile transposed: Qt[d][r]
#pragma unroll
    for (int it = 0; it < 4; it++) {
        int idx = tid + it * 256;
        int r = idx >> 4;
        int d0 = (idx & 15) * 4;
        float4 v = *(const float4*)(Qg + qbase + (size_t)r * INNER + d0);
        Qt[(d0 + 0) * SPAD + r] = v.x;
        Qt[(d0 + 1) * SPAD + r] = v.y;
        Qt[(d0 + 2) * SPAD + r] = v.z;
        Qt[(d0 + 3) * SPAD + r] = v.w;
    }
    if (tid < 64) { mrow[tid] = -INFINITY; lrow[tid] = 0.f; }

    float acc[4][4];
#pragma unroll
    for (int i = 0; i < 4; i++)
#pragma unroll
        for (int j = 0; j < 4; j++) acc[i][j] = 0.f;

    const int r0 = (tid >> 4) * 4;   // query-row micro-tile base
    const int c0 = (tid & 15) * 4;   // kv-col / out-col micro-tile base
    const int sr = tid >> 2;         // softmax row
    const int sg = tid & 3;          // softmax lane-in-row

    for (int t = 0; t < NC / 64; t++) {
        const int kv0 = t * 64;
        // Load K (transposed) and V (direct) tiles
#pragma unroll
        for (int it = 0; it < 4; it++) {
            int idx = tid + it * 256;
            int rr = idx >> 4;
            int d0 = (idx & 15) * 4;
            const float4 kv = *(const float4*)(Kg + kbase + (size_t)(kv0 + rr) * INNER + d0);
            Kt[(d0 + 0) * SPAD + rr] = kv.x;
            Kt[(d0 + 1) * SPAD + rr] = kv.y;
            Kt[(d0 + 2) * SPAD + rr] = kv.z;
            Kt[(d0 + 3) * SPAD + rr] = kv.w;
            const float4 vv = *(const float4*)(Vg + kbase + (size_t)(kv0 + rr) * INNER + d0);
            *(float4*)&Vs[rr * SPAD + d0] = vv;
        }
        __syncthreads();

        // S = Q @ K^T  (4x4 micro-tile per thread)
        float s[4][4];
#pragma unroll
        for (int i = 0; i < 4; i++)
#pragma unroll
            for (int j = 0; j < 4; j++) s[i][j] = 0.f;
#pragma unroll 4
        for (int d = 0; d < 64; d++) {
            float4 qv = *(float4*)&Qt[d * SPAD + r0];
            float4 kv = *(float4*)&Kt[d * SPAD + c0];
            float qa[4] = {qv.x, qv.y, qv.z, qv.w};
            float ka[4] = {kv.x, kv.y, kv.z, kv.w};
#pragma unroll
            for (int i = 0; i < 4; i++)
#pragma unroll
                for (int j = 0; j < 4; j++) s[i][j] = fmaf(qa[i], ka[j], s[i][j]);
        }
        // store transposed, scaled
#pragma unroll
        for (int j = 0; j < 4; j++)
#pragma unroll
            for (int i = 0; i < 4; i++)
                St[(c0 + j) * SPAD + (r0 + i)] = s[i][j] * 0.125f;
        __syncthreads();

        // Online softmax: 4 lanes per row, 16 cols each (c = sg + 4*cc)
        float mx = -INFINITY;
#pragma unroll
        for (int cc = 0; cc < 16; cc++) {
            int c = sg + cc * 4;
            mx = fmaxf(mx, St[c * SPAD + sr]);
        }
        mx = fmaxf(mx, __shfl_xor_sync(0xffffffffu, mx, 1));
        mx = fmaxf(mx, __shfl_xor_sync(0xffffffffu, mx, 2));
        const float mprev = mrow[sr];
        const float mnew = fmaxf(mprev, mx);
        const float alpha = __expf(mprev - mnew);
        float psum = 0.f;
#pragma unroll
        for (int cc = 0; cc < 16; cc++) {
            int c = sg + cc * 4;
            float p = __expf(St[c * SPAD + sr] - mnew);
            St[c * SPAD + sr] = p;
            psum += p;
        }
        psum += __shfl_xor_sync(0xffffffffu, psum, 1);
        psum += __shfl_xor_sync(0xffffffffu, psum, 2);
        if (sg == 0) {
            lrow[sr] = lrow[sr] * alpha + psum;
            mrow[sr] = mnew;
            arow[sr] = alpha;
        }
        __syncthreads();

        // O = O*alpha + P @ V
#pragma unroll
        for (int i = 0; i < 4; i++) {
            float al = arow[r0 + i];
#pragma unroll
            for (int j = 0; j < 4; j++) acc[i][j] *= al;
        }
#pragma unroll 4
        for (int k = 0; k < 64; k++) {
            float4 pv = *(float4*)&St[k * SPAD + r0];
            float4 vv = *(float4*)&Vs[k * SPAD + c0];
            float pa[4] = {pv.x, pv.y, pv.z, pv.w};
            float va[4] = {vv.x, vv.y, vv.z, vv.w};
#pragma unroll
            for (int i = 0; i < 4; i++)
#pragma unroll
                for (int j = 0; j < 4; j++) acc[i][j] = fmaf(pa[i], va[j], acc[i][j]);
        }
        __syncthreads();
    }

    // Epilogue: divide by row sums, write out [b, i, h*64 + d]
#pragma unroll
    for (int i = 0; i < 4; i++) {
        float inv = 1.f / lrow[r0 + i];
        float4 o = make_float4(acc[i][0] * inv, acc[i][1] * inv,
                               acc[i][2] * inv, acc[i][3] * inv);
        *(float4*)(Og + qbase + (size_t)(r0 + i) * INNER + c0) = o;
    }
}

// ---------------------------------------------------------------------------
extern "C" void kernel_launch(void* const* d_in, const int* in_sizes, int n_in,
                              void* d_out, int out_size)
{
    const float* x   = (const float*)d_in[0];  // [4,2048,1024]
    const float* ctx = (const float*)d_in[1];  // [4,2048,768]
    const float* Wq  = (const float*)d_in[2];  // [1024,512]
    const float* Wk  = (const float*)d_in[3];  // [768,512]
    const float* Wv  = (const float*)d_in[4];  // [768,512]
    const float* Wo  = (const float*)d_in[5];  // [512,1024]
    const float* bo  = (const float*)d_in[6];  // [1024]
    float* out = (float*)d_out;                // [4,2048,1024]

    float *qp, *kp, *vp, *aop;
    cudaGetSymbolAddress((void**)&qp, g_Q);
    cudaGetSymbolAddress((void**)&kp, g_K);
    cudaGetSymbolAddress((void**)&vp, g_V);
    cudaGetSymbolAddress((void**)&aop, g_AO);

    const int M = BATCH * NQ;  // 8192
    dim3 blk(256);

    // Projections
    sgemm_kernel<<<dim3(INNER / 128, M / 128), blk>>>(x,   Wq, nullptr, qp, M, INNER, DQ);
    sgemm_kernel<<<dim3(INNER / 128, M / 128), blk>>>(ctx, Wk, nullptr, kp, M, INNER, DC);
    sgemm_kernel<<<dim3(INNER / 128, M / 128), blk>>>(ctx, Wv, nullptr, vp, M, INNER, DC);

    // Flash attention
    const int smem = (4 * 64 * SPAD + 3 * 64) * sizeof(float);  // 70400 B
    cudaFuncSetAttribute(flash_kernel, cudaFuncAttributeMaxDynamicSharedMemorySize, smem);
    flash_kernel<<<dim3(NQ / 64, NHEADS, BATCH), blk, smem>>>(qp, kp, vp, aop);

    // Output projection + bias
    sgemm_kernel<<<dim3(DQ / 128, M / 128), blk>>>(aop, Wo, bo, out, M, DQ, INNER);
}

// round 3
// speedup vs baseline: 1.2357x; 1.2357x over previous
#include <cuda_runtime.h>
#include <cuda_bf16.h>
#include <math.h>
#include <stdint.h>

#define NHEADS 8
#define DIMH   64
#define BATCH  4
#define NQ     2048
#define NC     2048
#define DQ     1024
#define DC     768
#define INNER  512
#define MROWS  (BATCH * NQ)   // 8192

// ---------------------------------------------------------------------------
// Scratch (allocation-free rule: __device__ globals)
// ---------------------------------------------------------------------------
__device__ float g_Q [MROWS * INNER];
__device__ float g_K [MROWS * INNER];
__device__ float g_V [MROWS * INNER];
__device__ float g_AO[MROWS * INNER];

__device__ __nv_bfloat16 g_xh[MROWS * DQ];
__device__ __nv_bfloat16 g_xl[MROWS * DQ];
__device__ __nv_bfloat16 g_ch[MROWS * DC];
__device__ __nv_bfloat16 g_cl[MROWS * DC];
__device__ __nv_bfloat16 g_aoh[MROWS * INNER];
__device__ __nv_bfloat16 g_aol[MROWS * INNER];

__device__ __nv_bfloat16 g_wqh[INNER * DQ];
__device__ __nv_bfloat16 g_wql[INNER * DQ];
__device__ __nv_bfloat16 g_wkh[INNER * DC];
__device__ __nv_bfloat16 g_wkl[INNER * DC];
__device__ __nv_bfloat16 g_wvh[INNER * DC];
__device__ __nv_bfloat16 g_wvl[INNER * DC];
__device__ __nv_bfloat16 g_woh[DQ * INNER];
__device__ __nv_bfloat16 g_wol[DQ * INNER];

// ---------------------------------------------------------------------------
// PTX helpers (all baseline features, legal on target sm_103)
// ---------------------------------------------------------------------------
__device__ __forceinline__ uint32_t smem_u32(const void* p) {
    uint32_t a;
    asm("{ .reg .u64 t; cvta.to.shared.u64 t, %1; cvt.u32.u64 %0, t; }" : "=r"(a) : "l"(p));
    return a;
}
__device__ __forceinline__ void cpa16(uint32_t dst, const void* src) {
    asm volatile("cp.async.cg.shared.global [%0], [%1], 16;" :: "r"(dst), "l"(src));
}
__device__ __forceinline__ void cpa_commit() { asm volatile("cp.async.commit_group;" ::: "memory"); }
__device__ __forceinline__ void cpa_wait0()  { asm volatile("cp.async.wait_group 0;" ::: "memory"); }
__device__ __forceinline__ void cpa_wait1()  { asm volatile("cp.async.wait_group 1;" ::: "memory"); }

__device__ __forceinline__ void ldsm4(uint32_t* r, uint32_t addr) {
    asm volatile("ldmatrix.sync.aligned.m8n8.x4.shared.b16 {%0,%1,%2,%3}, [%4];"
                 : "=r"(r[0]), "=r"(r[1]), "=r"(r[2]), "=r"(r[3]) : "r"(addr));
}
__device__ __forceinline__ void mma16816(float* c, const uint32_t* a, const uint32_t* b) {
    asm volatile(
        "mma.sync.aligned.m16n8k16.row.col.f32.bf16.bf16.f32 "
        "{%0,%1,%2,%3}, {%4,%5,%6,%7}, {%8,%9}, {%0,%1,%2,%3};"
        : "+f"(c[0]), "+f"(c[1]), "+f"(c[2]), "+f"(c[3])
        : "r"(a[0]), "r"(a[1]), "r"(a[2]), "r"(a[3]), "r"(b[0]), "r"(b[1]));
}

// ---------------------------------------------------------------------------
// Conversions: fp32 -> (bf16 hi, bf16 lo)
// ---------------------------------------------------------------------------
__global__ void conv_split_kernel(const float* __restrict__ A,
                                  __nv_bfloat16* __restrict__ H,
                                  __nv_bfloat16* __restrict__ L, int n4)
{
    int i = blockIdx.x * blockDim.x + threadIdx.x;
    if (i >= n4) return;
    float4 v = ((const float4*)A)[i];
    float a[4] = {v.x, v.y, v.z, v.w};
    __nv_bfloat162 h2[2], l2[2];
#pragma unroll
    for (int j = 0; j < 2; j++) {
        __nv_bfloat16 h0 = __float2bfloat16_rn(a[2 * j]);
        __nv_bfloat16 h1 = __float2bfloat16_rn(a[2 * j + 1]);
        __nv_bfloat16 l0 = __float2bfloat16_rn(a[2 * j] - __bfloat162float(h0));
        __nv_bfloat16 l1 = __float2bfloat16_rn(a[2 * j + 1] - __bfloat162float(h1));
        h2[j] = __nv_bfloat162(h0, h1);
        l2[j] = __nv_bfloat162(l0, l1);
    }
    ((__nv_bfloat162*)H)[2 * i] = h2[0];
    ((__nv_bfloat162*)H)[2 * i + 1] = h2[1];
    ((__nv_bfloat162*)L)[2 * i] = l2[0];
    ((__nv_bfloat162*)L)[2 * i + 1] = l2[1];
}

// W [K,N] fp32 -> Th, Tl [N,K] bf16 (transpose + split)
__global__ void convT_kernel(const float* __restrict__ W,
                             __nv_bfloat16* __restrict__ Th,
                             __nv_bfloat16* __restrict__ Tl, int K, int N)
{
    __shared__ float t[32][33];
    int k0 = blockIdx.y * 32, n0 = blockIdx.x * 32;
    int tx = threadIdx.x, ty = threadIdx.y;
#pragma unroll
    for (int i = 0; i < 32; i += 8)
        t[ty + i][tx] = W[(size_t)(k0 + ty + i) * N + n0 + tx];
    __syncthreads();
#pragma unroll
    for (int i = 0; i < 32; i += 8) {
        float v = t[tx][ty + i];
        __nv_bfloat16 h = __float2bfloat16_rn(v);
        __nv_bfloat16 l = __float2bfloat16_rn(v - __bfloat162float(h));
        Th[(size_t)(n0 + ty + i) * K + k0 + tx] = h;
        Tl[(size_t)(n0 + ty + i) * K + k0 + tx] = l;
    }
}

// ---------------------------------------------------------------------------
// mma.sync bf16-split GEMM: C = Ah@Bh^T + Al@Bh^T + Ah@Bl^T (+ bias)
// A*: [M,K] bf16 row-major. B*: [N,K] bf16 row-major. C: [M,N] fp32.
// CTA tile 128x128, BK=32, 8 warps (warp tile 32x64), cp.async double buffer.
// ---------------------------------------------------------------------------
#define SMP 40   // smem row pitch in bf16 (80B): conflict-free ldmatrix

__global__ __launch_bounds__(256) void mma_gemm3_kernel(
    const __nv_bfloat16* __restrict__ Ah, const __nv_bfloat16* __restrict__ Al,
    const __nv_bfloat16* __restrict__ Bh, const __nv_bfloat16* __restrict__ Bl,
    const float* __restrict__ bias, float* __restrict__ C,
    int M, int N, int K)
{
    __shared__ __nv_bfloat16 Asm[2][128][SMP];
    __shared__ __nv_bfloat16 Bsm[2][128][SMP];

    const int tid = threadIdx.x;
    const int wid = tid >> 5;
    const int lane = tid & 31;
    const int m0 = blockIdx.y * 128;
    const int n0 = blockIdx.x * 128;
    const int wm = wid & 3;     // 4 warps along M (32 rows each)
    const int wn = wid >> 2;    // 2 warps along N (64 cols each)

    const int nkt = K >> 5;
    const int total = 3 * nkt;

    auto issue_chunk = [&](int g, int buf) {
        const int seg = g / nkt;
        const int kt = g - seg * nkt;
        const __nv_bfloat16* Aseg = (seg == 1) ? Al : Ah;
        const __nv_bfloat16* Bseg = (seg == 2) ? Bl : Bh;
        const int k0 = kt << 5;
#pragma unroll
        for (int i = 0; i < 2; i++) {
            const int c = tid + (i << 8);       // 0..511
            const int row = c >> 2;
            const int col = (c & 3) << 3;       // 0,8,16,24
            cpa16(smem_u32(&Asm[buf][row][col]), Aseg + (size_t)(m0 + row) * K + k0 + col);
            cpa16(smem_u32(&Bsm[buf][row][col]), Bseg + (size_t)(n0 + row) * K + k0 + col);
        }
        cpa_commit();
    };

    float acc[2][8][4];
#pragma unroll
    for (int mi = 0; mi < 2; mi++)
#pragma unroll
        for (int nj = 0; nj < 8; nj++)
#pragma unroll
            for (int r = 0; r < 4; r++) acc[mi][nj][r] = 0.f;

    // ldmatrix lane-derived addressing
    const int a_r = lane & 15;              // row within m16
    const int a_k = (lane >> 4) << 3;       // k-offset 0/8
    const int b_r = ((lane >> 4) << 3) + (lane & 7);   // row within n16
    const int b_k = ((lane >> 3) & 1) << 3;            // k-offset 0/8

    issue_chunk(0, 0);
#pragma unroll 1
    for (int g = 0; g < total; g++) {
        const int buf = g & 1;
        if (g + 1 < total) { issue_chunk(g + 1, buf ^ 1); cpa_wait1(); }
        else cpa_wait0();
        __syncthreads();

#pragma unroll
        for (int ks = 0; ks < 2; ks++) {
            uint32_t af[2][4], bfr[4][4];
            ldsm4(af[0], smem_u32(&Asm[buf][wm * 32 + a_r][ks * 16 + a_k]));
            ldsm4(af[1], smem_u32(&Asm[buf][wm * 32 + 16 + a_r][ks * 16 + a_k]));
#pragma unroll
            for (int ni = 0; ni < 4; ni++)
                ldsm4(bfr[ni], smem_u32(&Bsm[buf][wn * 64 + ni * 16 + b_r][ks * 16 + b_k]));
#pragma unroll
            for (int mi = 0; mi < 2; mi++)
#pragma unroll
                for (int nj = 0; nj < 8; nj++)
                    mma16816(acc[mi][nj], af[mi], &bfr[nj >> 1][(nj & 1) * 2]);
        }
        __syncthreads();
    }

    // Epilogue
    const int er = lane >> 2;
    const int ec = (lane & 3) << 1;
#pragma unroll
    for (int mi = 0; mi < 2; mi++) {
        const int row = m0 + wm * 32 + mi * 16 + er;
#pragma unroll
        for (int nj = 0; nj < 8; nj++) {
            const int col = n0 + wn * 64 + nj * 8 + ec;
            float b0 = 0.f, b1 = 0.f;
            if (bias) { b0 = bias[col]; b1 = bias[col + 1]; }
            float2 v0 = make_float2(acc[mi][nj][0] + b0, acc[mi][nj][1] + b1);
            float2 v1 = make_float2(acc[mi][nj][2] + b0, acc[mi][nj][3] + b1);
            *(float2*)(C + (size_t)row * N + col) = v0;
            *(float2*)(C + (size_t)(row + 8) * N + col) = v1;
        }
    }
}

// ---------------------------------------------------------------------------
// Flash attention, fp32 (unchanged)
// ---------------------------------------------------------------------------
#define SPAD 68

__global__ __launch_bounds__(256) void flash_kernel(
    const float* __restrict__ Qg, const float* __restrict__ Kg,
    const float* __restrict__ Vg, float* __restrict__ Og)
{
    extern __shared__ float sm[];
    float* Qt = sm;
    float* Kt = Qt + 64 * SPAD;
    float* Vs = Kt + 64 * SPAD;
    float* St = Vs + 64 * SPAD;
    float* mrow = St + 64 * SPAD;
    float* lrow = mrow + 64;
    float* arow = lrow + 64;

    const int tid = threadIdx.x;
    const int qt = blockIdx.x, h = blockIdx.y, b = blockIdx.z;
    const size_t qbase = ((size_t)b * NQ + (size_t)qt * 64) * INNER + h * DIMH;
    const size_t kbase = ((size_t)b * NC) * INNER + h * DIMH;

#pragma unroll
    for (int it = 0; it < 4; it++) {
        int idx = tid + it * 256;
        int r = idx >> 4;
        int d0 = (idx & 15) * 4;
        float4 v = *(const float4*)(Qg + qbase + (size_t)r * INNER + d0);
        Qt[(d0 + 0) * SPAD + r] = v.x;
        Qt[(d0 + 1) * SPAD + r] = v.y;
        Qt[(d0 + 2) * SPAD + r] = v.z;
        Qt[(d0 + 3) * SPAD + r] = v.w;
    }
    if (tid < 64) { mrow[tid] = -INFINITY; lrow[tid] = 0.f; }

    float acc[4][4];
#pragma unroll
    for (int i = 0; i < 4; i++)
#pragma unroll
        for (int j = 0; j < 4; j++) acc[i][j] = 0.f;

    const int r0 = (tid >> 4) * 4;
    const int c0 = (tid & 15) * 4;
    const int sr = tid >> 2;
    const int sg = tid & 3;

    for (int t = 0; t < NC / 64; t++) {
        const int kv0 = t * 64;
#pragma unroll
        for (int it = 0; it < 4; it++) {
            int idx = tid + it * 256;
            int rr = idx >> 4;
            int d0 = (idx & 15) * 4;
            const float4 kv = *(const float4*)(Kg + kbase + (size_t)(kv0 + rr) * INNER + d0);
            Kt[(d0 + 0) * SPAD + rr] = kv.x;
            Kt[(d0 + 1) * SPAD + rr] = kv.y;
            Kt[(d0 + 2) * SPAD + rr] = kv.z;
            Kt[(d0 + 3) * SPAD + rr] = kv.w;
            const float4 vv = *(const float4*)(Vg + kbase + (size_t)(kv0 + rr) * INNER + d0);
            *(float4*)&Vs[rr * SPAD + d0] = vv;
        }
        __syncthreads();

        float s[4][4];
#pragma unroll
        for (int i = 0; i < 4; i++)
#pragma unroll
            for (int j = 0; j < 4; j++) s[i][j] = 0.f;
#pragma unroll 4
        for (int d = 0; d < 64; d++) {
            float4 qv = *(float4*)&Qt[d * SPAD + r0];
            float4 kv = *(float4*)&Kt[d * SPAD + c0];
            float qa[4] = {qv.x, qv.y, qv.z, qv.w};
            float ka[4] = {kv.x, kv.y, kv.z, kv.w};
#pragma unroll
            for (int i = 0; i < 4; i++)
#pragma unroll
                for (int j = 0; j < 4; j++) s[i][j] = fmaf(qa[i], ka[j], s[i][j]);
        }
#pragma unroll
        for (int j = 0; j < 4; j++)
#pragma unroll
            for (int i = 0; i < 4; i++)
                St[(c0 + j) * SPAD + (r0 + i)] = s[i][j] * 0.125f;
        __syncthreads();

        float mx = -INFINITY;
#pragma unroll
        for (int cc = 0; cc < 16; cc++) {
            int c = sg + cc * 4;
            mx = fmaxf(mx, St[c * SPAD + sr]);
        }
        mx = fmaxf(mx, __shfl_xor_sync(0xffffffffu, mx, 1));
        mx = fmaxf(mx, __shfl_xor_sync(0xffffffffu, mx, 2));
        const float mprev = mrow[sr];
        const float mnew = fmaxf(mprev, mx);
        const float alpha = __expf(mprev - mnew);
        float psum = 0.f;
#pragma unroll
        for (int cc = 0; cc < 16; cc++) {
            int c = sg + cc * 4;
            float p = __expf(St[c * SPAD + sr] - mnew);
            St[c * SPAD + sr] = p;
            psum += p;
        }
        psum += __shfl_xor_sync(0xffffffffu, psum, 1);
        psum += __shfl_xor_sync(0xffffffffu, psum, 2);
        if (sg == 0) {
            lrow[sr] = lrow[sr] * alpha + psum;
            mrow[sr] = mnew;
            arow[sr] = alpha;
        }
        __syncthreads();

#pragma unroll
        for (int i = 0; i < 4; i++) {
            float al = arow[r0 + i];
#pragma unroll
            for (int j = 0; j < 4; j++) acc[i][j] *= al;
        }
#pragma unroll 4
        for (int k = 0; k < 64; k++) {
            float4 pv = *(float4*)&St[k * SPAD + r0];
            float4 vv = *(float4*)&Vs[k * SPAD + c0];
            float pa[4] = {pv.x, pv.y, pv.z, pv.w};
            float va[4] = {vv.x, vv.y, vv.z, vv.w};
#pragma unroll
            for (int i = 0; i < 4; i++)
#pragma unroll
                for (int j = 0; j < 4; j++) acc[i][j] = fmaf(pa[i], va[j], acc[i][j]);
        }
        __syncthreads();
    }

#pragma unroll
    for (int i = 0; i < 4; i++) {
        float inv = 1.f / lrow[r0 + i];
        float4 o = make_float4(acc[i][0] * inv, acc[i][1] * inv,
                               acc[i][2] * inv, acc[i][3] * inv);
        *(float4*)(Og + qbase + (size_t)(r0 + i) * INNER + c0) = o;
    }
}

// ---------------------------------------------------------------------------
extern "C" void kernel_launch(void* const* d_in, const int* in_sizes, int n_in,
                              void* d_out, int out_size)
{
    const float* x   = (const float*)d_in[0];
    const float* ctx = (const float*)d_in[1];
    const float* Wq  = (const float*)d_in[2];
    const float* Wk  = (const float*)d_in[3];
    const float* Wv  = (const float*)d_in[4];
    const float* Wo  = (const float*)d_in[5];
    const float* bo  = (const float*)d_in[6];
    float* out = (float*)d_out;

    float *qp, *kp, *vp, *aop;
    cudaGetSymbolAddress((void**)&qp, g_Q);
    cudaGetSymbolAddress((void**)&kp, g_K);
    cudaGetSymbolAddress((void**)&vp, g_V);
    cudaGetSymbolAddress((void**)&aop, g_AO);
    __nv_bfloat16 *xh, *xl, *ch, *cl, *aoh, *aol;
    __nv_bfloat16 *wqh, *wql, *wkh, *wkl, *wvh, *wvl, *woh, *wol;
    cudaGetSymbolAddress((void**)&xh, g_xh);  cudaGetSymbolAddress((void**)&xl, g_xl);
    cudaGetSymbolAddress((void**)&ch, g_ch);  cudaGetSymbolAddress((void**)&cl, g_cl);
    cudaGetSymbolAddress((void**)&aoh, g_aoh); cudaGetSymbolAddress((void**)&aol, g_aol);
    cudaGetSymbolAddress((void**)&wqh, g_wqh); cudaGetSymbolAddress((void**)&wql, g_wql);
    cudaGetSymbolAddress((void**)&wkh, g_wkh); cudaGetSymbolAddress((void**)&wkl, g_wkl);
    cudaGetSymbolAddress((void**)&wvh, g_wvh); cudaGetSymbolAddress((void**)&wvl, g_wvl);
    cudaGetSymbolAddress((void**)&woh, g_woh); cudaGetSymbolAddress((void**)&wol, g_wol);

    // ---- conversions ----
    {
        int n4 = MROWS * DQ / 4;
        conv_split_kernel<<<(n4 + 255) / 256, 256>>>(x, xh, xl, n4);
        n4 = MROWS * DC / 4;
        conv_split_kernel<<<(n4 + 255) / 256, 256>>>(ctx, ch, cl, n4);
    }
    convT_kernel<<<dim3(INNER / 32, DQ / 32), dim3(32, 8)>>>(Wq, wqh, wql, DQ, INNER);
    convT_kernel<<<dim3(INNER / 32, DC / 32), dim3(32, 8)>>>(Wk, wkh, wkl, DC, INNER);
    convT_kernel<<<dim3(INNER / 32, DC / 32), dim3(32, 8)>>>(Wv, wvh, wvl, DC, INNER);
    convT_kernel<<<dim3(DQ / 32, INNER / 32), dim3(32, 8)>>>(Wo, woh, wol, INNER, DQ);

    // ---- projections (mma.sync split GEMM) ----
    mma_gemm3_kernel<<<dim3(INNER / 128, MROWS / 128), 256>>>(
        xh, xl, wqh, wql, nullptr, qp, MROWS, INNER, DQ);
    mma_gemm3_kernel<<<dim3(INNER / 128, MROWS / 128), 256>>>(
        ch, cl, wkh, wkl, nullptr, kp, MROWS, INNER, DC);
    mma_gemm3_kernel<<<dim3(INNER / 128, MROWS / 128), 256>>>(
        ch, cl, wvh, wvl, nullptr, vp, MROWS, INNER, DC);

    // ---- attention ----
    const int smem = (4 * 64 * SPAD + 3 * 64) * sizeof(float);
    cudaFuncSetAttribute(flash_kernel, cudaFuncAttributeMaxDynamicSharedMemorySize, smem);
    flash_kernel<<<dim3(NQ / 64, NHEADS, BATCH), 256, smem>>>(qp, kp, vp, aop);

    // ---- output projection ----
    {
        int n4 = MROWS * INNER / 4;
        conv_split_kernel<<<(n4 + 255) / 256, 256>>>(aop, aoh, aol, n4);
    }
    mma_gemm3_kernel<<<dim3(DQ / 128, MROWS / 128), 256>>>(
        aoh, aol, woh, wol, bo, out, MROWS, DQ, INNER);
}

// round 4
// speedup vs baseline: 2.5645x; 2.0753x over previous
#include <cuda_runtime.h>
#include <cuda_bf16.h>
#include <math.h>
#include <stdint.h>

#define NHEADS 8
#define DIMH   64
#define BATCH  4
#define NQ     2048
#define NC     2048
#define DQ     1024
#define DC     768
#define INNER  512
#define MROWS  (BATCH * NQ)   // 8192

// ---------------------------------------------------------------------------
// Scratch (allocation-free rule: __device__ globals) — all bf16 hi/lo pairs
// ---------------------------------------------------------------------------
__device__ __nv_bfloat16 g_xh[MROWS * DQ];
__device__ __nv_bfloat16 g_xl[MROWS * DQ];
__device__ __nv_bfloat16 g_ch[MROWS * DC];
__device__ __nv_bfloat16 g_cl[MROWS * DC];

__device__ __nv_bfloat16 g_qh[MROWS * INNER];
__device__ __nv_bfloat16 g_ql[MROWS * INNER];
__device__ __nv_bfloat16 g_kh[MROWS * INNER];
__device__ __nv_bfloat16 g_kl[MROWS * INNER];
__device__ __nv_bfloat16 g_vh[MROWS * INNER];
__device__ __nv_bfloat16 g_vl[MROWS * INNER];
__device__ __nv_bfloat16 g_aoh[MROWS * INNER];
__device__ __nv_bfloat16 g_aol[MROWS * INNER];

__device__ __nv_bfloat16 g_wqh[INNER * DQ];
__device__ __nv_bfloat16 g_wql[INNER * DQ];
__device__ __nv_bfloat16 g_wkh[INNER * DC];
__device__ __nv_bfloat16 g_wkl[INNER * DC];
__device__ __nv_bfloat16 g_wvh[INNER * DC];
__device__ __nv_bfloat16 g_wvl[INNER * DC];
__device__ __nv_bfloat16 g_woh[DQ * INNER];
__device__ __nv_bfloat16 g_wol[DQ * INNER];

// ---------------------------------------------------------------------------
// PTX helpers (baseline features, legal on target sm_103)
// ---------------------------------------------------------------------------
__device__ __forceinline__ uint32_t smem_u32(const void* p) {
    uint32_t a;
    asm("{ .reg .u64 t; cvta.to.shared.u64 t, %1; cvt.u32.u64 %0, t; }" : "=r"(a) : "l"(p));
    return a;
}
__device__ __forceinline__ void cpa16(uint32_t dst, const void* src) {
    asm volatile("cp.async.cg.shared.global [%0], [%1], 16;" :: "r"(dst), "l"(src));
}
__device__ __forceinline__ void cpa_commit() { asm volatile("cp.async.commit_group;" ::: "memory"); }
__device__ __forceinline__ void cpa_wait0()  { asm volatile("cp.async.wait_group 0;" ::: "memory"); }
__device__ __forceinline__ void cpa_wait1()  { asm volatile("cp.async.wait_group 1;" ::: "memory"); }

__device__ __forceinline__ void ldsm4(uint32_t* r, uint32_t addr) {
    asm volatile("ldmatrix.sync.aligned.m8n8.x4.shared.b16 {%0,%1,%2,%3}, [%4];"
                 : "=r"(r[0]), "=r"(r[1]), "=r"(r[2]), "=r"(r[3]) : "r"(addr));
}
__device__ __forceinline__ void ldsm4t(uint32_t* r, uint32_t addr) {
    asm volatile("ldmatrix.sync.aligned.m8n8.x4.trans.shared.b16 {%0,%1,%2,%3}, [%4];"
                 : "=r"(r[0]), "=r"(r[1]), "=r"(r[2]), "=r"(r[3]) : "r"(addr));
}
__device__ __forceinline__ void mma16816(float* c, const uint32_t* a, const uint32_t* b) {
    asm volatile(
        "mma.sync.aligned.m16n8k16.row.col.f32.bf16.bf16.f32 "
        "{%0,%1,%2,%3}, {%4,%5,%6,%7}, {%8,%9}, {%0,%1,%2,%3};"
        : "+f"(c[0]), "+f"(c[1]), "+f"(c[2]), "+f"(c[3])
        : "r"(a[0]), "r"(a[1]), "r"(a[2]), "r"(a[3]), "r"(b[0]), "r"(b[1]));
}

__device__ __forceinline__ uint32_t pack_bf16x2(float lo, float hi) {
    __nv_bfloat162 t = __floats2bfloat162_rn(lo, hi);
    return *reinterpret_cast<uint32_t*>(&t);
}
__device__ __forceinline__ uint32_t pack_residual(float lo, float hi, uint32_t hpack) {
    __nv_bfloat162 t = *reinterpret_cast<__nv_bfloat162*>(&hpack);
    return pack_bf16x2(lo - __low2float(t), hi - __high2float(t));
}

// ---------------------------------------------------------------------------
// Conversions
// ---------------------------------------------------------------------------
__global__ void conv_split_kernel(const float* __restrict__ A,
                                  __nv_bfloat16* __restrict__ H,
                                  __nv_bfloat16* __restrict__ L, int n4)
{
    int i = blockIdx.x * blockDim.x + threadIdx.x;
    if (i >= n4) return;
    float4 v = ((const float4*)A)[i];
    float a[4] = {v.x, v.y, v.z, v.w};
    __nv_bfloat162 h2[2], l2[2];
#pragma unroll
    for (int j = 0; j < 2; j++) {
        __nv_bfloat16 h0 = __float2bfloat16_rn(a[2 * j]);
        __nv_bfloat16 h1 = __float2bfloat16_rn(a[2 * j + 1]);
        __nv_bfloat16 l0 = __float2bfloat16_rn(a[2 * j] - __bfloat162float(h0));
        __nv_bfloat16 l1 = __float2bfloat16_rn(a[2 * j + 1] - __bfloat162float(h1));
        h2[j] = __nv_bfloat162(h0, h1);
        l2[j] = __nv_bfloat162(l0, l1);
    }
    ((__nv_bfloat162*)H)[2 * i] = h2[0];
    ((__nv_bfloat162*)H)[2 * i + 1] = h2[1];
    ((__nv_bfloat162*)L)[2 * i] = l2[0];
    ((__nv_bfloat162*)L)[2 * i + 1] = l2[1];
}

__global__ void convT_kernel(const float* __restrict__ W,
                             __nv_bfloat16* __restrict__ Th,
                             __nv_bfloat16* __restrict__ Tl, int K, int N)
{
    __shared__ float t[32][33];
    int k0 = blockIdx.y * 32, n0 = blockIdx.x * 32;
    int tx = threadIdx.x, ty = threadIdx.y;
#pragma unroll
    for (int i = 0; i < 32; i += 8)
        t[ty + i][tx] = W[(size_t)(k0 + ty + i) * N + n0 + tx];
    __syncthreads();
#pragma unroll
    for (int i = 0; i < 32; i += 8) {
        float v = t[tx][ty + i];
        __nv_bfloat16 h = __float2bfloat16_rn(v);
        __nv_bfloat16 l = __float2bfloat16_rn(v - __bfloat162float(h));
        Th[(size_t)(n0 + ty + i) * K + k0 + tx] = h;
        Tl[(size_t)(n0 + ty + i) * K + k0 + tx] = l;
    }
}

// ---------------------------------------------------------------------------
// mma.sync split GEMM.  If Ch != null: write bf16 hi/lo pair outputs.
// Else: write fp32 C (+ bias).
// ---------------------------------------------------------------------------
#define SMP 40

__global__ __launch_bounds__(256) void mma_gemm3_kernel(
    const __nv_bfloat16* __restrict__ Ah, const __nv_bfloat16* __restrict__ Al,
    const __nv_bfloat16* __restrict__ Bh, const __nv_bfloat16* __restrict__ Bl,
    const float* __restrict__ bias, float* __restrict__ Cf,
    __nv_bfloat16* __restrict__ Ch, __nv_bfloat16* __restrict__ Cl,
    int M, int N, int K)
{
    __shared__ __nv_bfloat16 Asm[2][128][SMP];
    __shared__ __nv_bfloat16 Bsm[2][128][SMP];

    const int tid = threadIdx.x;
    const int wid = tid >> 5;
    const int lane = tid & 31;
    const int m0 = blockIdx.y * 128;
    const int n0 = blockIdx.x * 128;
    const int wm = wid & 3;
    const int wn = wid >> 2;

    const int nkt = K >> 5;
    const int total = 3 * nkt;

    auto issue_chunk = [&](int g, int buf) {
        const int seg = g / nkt;
        const int kt = g - seg * nkt;
        const __nv_bfloat16* Aseg = (seg == 1) ? Al : Ah;
        const __nv_bfloat16* Bseg = (seg == 2) ? Bl : Bh;
        const int k0 = kt << 5;
#pragma unroll
        for (int i = 0; i < 2; i++) {
            const int c = tid + (i << 8);
            const int row = c >> 2;
            const int col = (c & 3) << 3;
            cpa16(smem_u32(&Asm[buf][row][col]), Aseg + (size_t)(m0 + row) * K + k0 + col);
            cpa16(smem_u32(&Bsm[buf][row][col]), Bseg + (size_t)(n0 + row) * K + k0 + col);
        }
        cpa_commit();
    };

    float acc[2][8][4];
#pragma unroll
    for (int mi = 0; mi < 2; mi++)
#pragma unroll
        for (int nj = 0; nj < 8; nj++)
#pragma unroll
            for (int r = 0; r < 4; r++) acc[mi][nj][r] = 0.f;

    const int a_r = lane & 15;
    const int a_k = (lane >> 4) << 3;
    const int b_r = ((lane >> 4) << 3) + (lane & 7);
    const int b_k = ((lane >> 3) & 1) << 3;

    issue_chunk(0, 0);
#pragma unroll 1
    for (int g = 0; g < total; g++) {
        const int buf = g & 1;
        if (g + 1 < total) { issue_chunk(g + 1, buf ^ 1); cpa_wait1(); }
        else cpa_wait0();
        __syncthreads();

#pragma unroll
        for (int ks = 0; ks < 2; ks++) {
            uint32_t af[2][4], bfr[4][4];
            ldsm4(af[0], smem_u32(&Asm[buf][wm * 32 + a_r][ks * 16 + a_k]));
            ldsm4(af[1], smem_u32(&Asm[buf][wm * 32 + 16 + a_r][ks * 16 + a_k]));
#pragma unroll
            for (int ni = 0; ni < 4; ni++)
                ldsm4(bfr[ni], smem_u32(&Bsm[buf][wn * 64 + ni * 16 + b_r][ks * 16 + b_k]));
#pragma unroll
            for (int mi = 0; mi < 2; mi++)
#pragma unroll
                for (int nj = 0; nj < 8; nj++)
                    mma16816(acc[mi][nj], af[mi], &bfr[nj >> 1][(nj & 1) * 2]);
        }
        __syncthreads();
    }

    const int er = lane >> 2;
    const int ec = (lane & 3) << 1;
#pragma unroll
    for (int mi = 0; mi < 2; mi++) {
        const int row = m0 + wm * 32 + mi * 16 + er;
#pragma unroll
        for (int nj = 0; nj < 8; nj++) {
            const int col = n0 + wn * 64 + nj * 8 + ec;
            if (Ch) {
                uint32_t h0 = pack_bf16x2(acc[mi][nj][0], acc[mi][nj][1]);
                uint32_t l0 = pack_residual(acc[mi][nj][0], acc[mi][nj][1], h0);
                uint32_t h1 = pack_bf16x2(acc[mi][nj][2], acc[mi][nj][3]);
                uint32_t l1 = pack_residual(acc[mi][nj][2], acc[mi][nj][3], h1);
                *(uint32_t*)(Ch + (size_t)row * N + col) = h0;
                *(uint32_t*)(Cl + (size_t)row * N + col) = l0;
                *(uint32_t*)(Ch + (size_t)(row + 8) * N + col) = h1;
                *(uint32_t*)(Cl + (size_t)(row + 8) * N + col) = l1;
            } else {
                float b0 = 0.f, b1 = 0.f;
                if (bias) { b0 = bias[col]; b1 = bias[col + 1]; }
                *(float2*)(Cf + (size_t)row * N + col) =
                    make_float2(acc[mi][nj][0] + b0, acc[mi][nj][1] + b1);
                *(float2*)(Cf + (size_t)(row + 8) * N + col) =
                    make_float2(acc[mi][nj][2] + b0, acc[mi][nj][3] + b1);
            }
        }
    }
}

// ---------------------------------------------------------------------------
// Tensor-core flash attention with split precision.
// Block = 128 q rows for one (b, h). 8 warps x 16 rows. kv tile 64.
// S = QhKh + QlKh + QhKl ; O = PhVh + PlVh + PhVl (P split in registers).
// ---------------------------------------------------------------------------
#define FPITCH 72
#define KVT    (64 * FPITCH)
#define FLASH_SMEM ((2 * 128 * FPITCH + 2 * 4 * KVT) * 2)   // 110592 bytes

__global__ __launch_bounds__(256) void flash_mma_kernel(
    const __nv_bfloat16* __restrict__ Qh_, const __nv_bfloat16* __restrict__ Ql_,
    const __nv_bfloat16* __restrict__ Kh_, const __nv_bfloat16* __restrict__ Kl_,
    const __nv_bfloat16* __restrict__ Vh_, const __nv_bfloat16* __restrict__ Vl_,
    __nv_bfloat16* __restrict__ AOh, __nv_bfloat16* __restrict__ AOl)
{
    extern __shared__ char fsmc[];
    __nv_bfloat16* fsm = (__nv_bfloat16*)fsmc;
    __nv_bfloat16* sQh = fsm;
    __nv_bfloat16* sQl = sQh + 128 * FPITCH;
    __nv_bfloat16* sKV = sQl + 128 * FPITCH;   // [buf][Kh,Kl,Vh,Vl][64*FPITCH]

    const int tid = threadIdx.x;
    const int wid = tid >> 5;
    const int lane = tid & 31;
    const int qt = blockIdx.x, h = blockIdx.y, b = blockIdx.z;
    const size_t qrow0 = (size_t)b * NQ + (size_t)qt * 128;
    const size_t krow0 = (size_t)b * NC;
    const int colbase = h * DIMH;

    auto issue_kv = [&](int t, int buf) {
        __nv_bfloat16* base = sKV + buf * 4 * KVT;
        const size_t gr = (krow0 + t * 64) * INNER + colbase;
#pragma unroll
        for (int i = 0; i < 2; i++) {
            const int idx = tid + (i << 8);      // 0..511
            const int r = idx >> 3;
            const int c = (idx & 7) << 3;
            const size_t go = gr + (size_t)r * INNER + c;
            const uint32_t so = smem_u32(base + r * FPITCH + c);
            cpa16(so + 0 * KVT * 2, Kh_ + go);
            cpa16(so + 1 * KVT * 2, Kl_ + go);
            cpa16(so + 2 * KVT * 2, Vh_ + go);
            cpa16(so + 3 * KVT * 2, Vl_ + go);
        }
        cpa_commit();
    };

    // Q tiles + first KV tile in one cp.async group
#pragma unroll
    for (int i = 0; i < 4; i++) {
        const int idx = tid + (i << 8);          // 0..1023
        const int r = idx >> 3;
        const int c = (idx & 7) << 3;
        const size_t go = (qrow0 + r) * INNER + colbase + c;
        cpa16(smem_u32(sQh + r * FPITCH + c), Qh_ + go);
        cpa16(smem_u32(sQl + r * FPITCH + c), Ql_ + go);
    }
    issue_kv(0, 0);

    // fragment addressing
    const int a_r = lane & 15;
    const int a_k = (lane >> 4) << 3;
    const int b_r = ((lane >> 4) << 3) + (lane & 7);
    const int b_k = ((lane >> 3) & 1) << 3;
    const int v_r = (((lane >> 3) & 1) << 3) + (lane & 7);
    const int v_c = (lane >> 4) << 3;
    const int wq = wid * 16;

    float acc[8][4];
#pragma unroll
    for (int j = 0; j < 8; j++)
#pragma unroll
        for (int r = 0; r < 4; r++) acc[j][r] = 0.f;
    float m0 = -INFINITY, m1 = -INFINITY, l0 = 0.f, l1 = 0.f;

    const int NT = NC / 64;
#pragma unroll 1
    for (int t = 0; t < NT; t++) {
        const int buf = t & 1;
        if (t + 1 < NT) { issue_kv(t + 1, buf ^ 1); cpa_wait1(); }
        else cpa_wait0();
        __syncthreads();

        __nv_bfloat16* kh = sKV + buf * 4 * KVT;
        __nv_bfloat16* kl = kh + KVT;
        __nv_bfloat16* vh = kh + 2 * KVT;
        __nv_bfloat16* vl = kh + 3 * KVT;

        // ---- S = Qh Kh^T + Ql Kh^T + Qh Kl^T ----
        float s[8][4];
#pragma unroll
        for (int j = 0; j < 8; j++)
#pragma unroll
            for (int r = 0; r < 4; r++) s[j][r] = 0.f;

#pragma unroll
        for (int kc = 0; kc < 4; kc++) {
            uint32_t aq[4], aql[4], bk[4][4];
            ldsm4(aq, smem_u32(&sQh[(wq + a_r) * FPITCH + kc * 16 + a_k]));
            ldsm4(aql, smem_u32(&sQl[(wq + a_r) * FPITCH + kc * 16 + a_k]));
#pragma unroll
            for (int nb = 0; nb < 4; nb++)
                ldsm4(bk[nb], smem_u32(&kh[(nb * 16 + b_r) * FPITCH + kc * 16 + b_k]));
#pragma unroll
            for (int j = 0; j < 8; j++) mma16816(s[j], aq, &bk[j >> 1][(j & 1) * 2]);
#pragma unroll
            for (int j = 0; j < 8; j++) mma16816(s[j], aql, &bk[j >> 1][(j & 1) * 2]);
#pragma unroll
            for (int nb = 0; nb < 4; nb++)
                ldsm4(bk[nb], smem_u32(&kl[(nb * 16 + b_r) * FPITCH + kc * 16 + b_k]));
#pragma unroll
            for (int j = 0; j < 8; j++) mma16816(s[j], aq, &bk[j >> 1][(j & 1) * 2]);
        }

        // ---- online softmax (rows er=lane>>2 and er+8; quad-local) ----
        float mx0 = -INFINITY, mx1 = -INFINITY;
#pragma unroll
        for (int j = 0; j < 8; j++) {
#pragma unroll
            for (int r = 0; r < 4; r++) s[j][r] *= 0.125f;
            mx0 = fmaxf(mx0, fmaxf(s[j][0], s[j][1]));
            mx1 = fmaxf(mx1, fmaxf(s[j][2], s[j][3]));
        }
        mx0 = fmaxf(mx0, __shfl_xor_sync(0xffffffffu, mx0, 1));
        mx0 = fmaxf(mx0, __shfl_xor_sync(0xffffffffu, mx0, 2));
        mx1 = fmaxf(mx1, __shfl_xor_sync(0xffffffffu, mx1, 1));
        mx1 = fmaxf(mx1, __shfl_xor_sync(0xffffffffu, mx1, 2));
        const float mn0 = fmaxf(m0, mx0);
        const float mn1 = fmaxf(m1, mx1);
        const float al0 = __expf(m0 - mn0);
        const float al1 = __expf(m1 - mn1);
        m0 = mn0; m1 = mn1;

        float ps0 = 0.f, ps1 = 0.f;
        uint32_t ph[8][2];
#pragma unroll
        for (int j = 0; j < 8; j++) {
            s[j][0] = __expf(s[j][0] - mn0);
            s[j][1] = __expf(s[j][1] - mn0);
            s[j][2] = __expf(s[j][2] - mn1);
            s[j][3] = __expf(s[j][3] - mn1);
            ps0 += s[j][0] + s[j][1];
            ps1 += s[j][2] + s[j][3];
            ph[j][0] = pack_bf16x2(s[j][0], s[j][1]);
            ph[j][1] = pack_bf16x2(s[j][2], s[j][3]);
        }
        l0 = l0 * al0 + ps0;
        l1 = l1 * al1 + ps1;
#pragma unroll
        for (int j = 0; j < 8; j++) {
            acc[j][0] *= al0; acc[j][1] *= al0;
            acc[j][2] *= al1; acc[j][3] *= al1;
        }

        // ---- O += Ph Vh + Pl Vh + Ph Vl ----
#pragma unroll
        for (int kc = 0; kc < 4; kc++) {
            uint32_t ap[4] = {ph[2 * kc][0], ph[2 * kc][1], ph[2 * kc + 1][0], ph[2 * kc + 1][1]};
            uint32_t apl[4];
            apl[0] = pack_residual(s[2 * kc][0], s[2 * kc][1], ph[2 * kc][0]);
            apl[1] = pack_residual(s[2 * kc][2], s[2 * kc][3], ph[2 * kc][1]);
            apl[2] = pack_residual(s[2 * kc + 1][0], s[2 * kc + 1][1], ph[2 * kc + 1][0]);
            apl[3] = pack_residual(s[2 * kc + 1][2], s[2 * kc + 1][3], ph[2 * kc + 1][1]);
            uint32_t bv[4][4];
#pragma unroll
            for (int nb = 0; nb < 4; nb++)
                ldsm4t(bv[nb], smem_u32(&vh[(kc * 16 + v_r) * FPITCH + nb * 16 + v_c]));
#pragma unroll
            for (int j = 0; j < 8; j++) mma16816(acc[j], ap, &bv[j >> 1][(j & 1) * 2]);
#pragma unroll
            for (int j = 0; j < 8; j++) mma16816(acc[j], apl, &bv[j >> 1][(j & 1) * 2]);
#pragma unroll
            for (int nb = 0; nb < 4; nb++)
                ldsm4t(bv[nb], smem_u32(&vl[(kc * 16 + v_r) * FPITCH + nb * 16 + v_c]));
#pragma unroll
            for (int j = 0; j < 8; j++) mma16816(acc[j], ap, &bv[j >> 1][(j & 1) * 2]);
        }
        __syncthreads();
    }

    // ---- epilogue: normalize, split to bf16 hi/lo, store ----
    l0 += __shfl_xor_sync(0xffffffffu, l0, 1);
    l0 += __shfl_xor_sync(0xffffffffu, l0, 2);
    l1 += __shfl_xor_sync(0xffffffffu, l1, 1);
    l1 += __shfl_xor_sync(0xffffffffu, l1, 2);
    const float inv0 = 1.f / l0;
    const float inv1 = 1.f / l1;
    const size_t row0 = qrow0 + wq + (lane >> 2);
    const size_t row1 = row0 + 8;
#pragma unroll
    for (int j = 0; j < 8; j++) {
        const int col = colbase + j * 8 + (lane & 3) * 2;
        float v0 = acc[j][0] * inv0, v1 = acc[j][1] * inv0;
        uint32_t hp = pack_bf16x2(v0, v1);
        *(uint32_t*)(AOh + row0 * INNER + col) = hp;
        *(uint32_t*)(AOl + row0 * INNER + col) = pack_residual(v0, v1, hp);
        float v2 = acc[j][2] * inv1, v3 = acc[j][3] * inv1;
        uint32_t hp1 = pack_bf16x2(v2, v3);
        *(uint32_t*)(AOh + row1 * INNER + col) = hp1;
        *(uint32_t*)(AOl + row1 * INNER + col) = pack_residual(v2, v3, hp1);
    }
}

// ---------------------------------------------------------------------------
extern "C" void kernel_launch(void* const* d_in, const int* in_sizes, int n_in,
                              void* d_out, int out_size)
{
    const float* x   = (const float*)d_in[0];
    const float* ctx = (const float*)d_in[1];
    const float* Wq  = (const float*)d_in[2];
    const float* Wk  = (const float*)d_in[3];
    const float* Wv  = (const float*)d_in[4];
    const float* Wo  = (const float*)d_in[5];
    const float* bo  = (const float*)d_in[6];
    float* out = (float*)d_out;

    __nv_bfloat16 *xh, *xl, *ch, *cl;
    __nv_bfloat16 *qh, *ql, *kh, *kl, *vh, *vl, *aoh, *aol;
    __nv_bfloat16 *wqh, *wql, *wkh, *wkl, *wvh, *wvl, *woh, *wol;
    cudaGetSymbolAddress((void**)&xh, g_xh);   cudaGetSymbolAddress((void**)&xl, g_xl);
    cudaGetSymbolAddress((void**)&ch, g_ch);   cudaGetSymbolAddress((void**)&cl, g_cl);
    cudaGetSymbolAddress((void**)&qh, g_qh);   cudaGetSymbolAddress((void**)&ql, g_ql);
    cudaGetSymbolAddress((void**)&kh, g_kh);   cudaGetSymbolAddress((void**)&kl, g_kl);
    cudaGetSymbolAddress((void**)&vh, g_vh);   cudaGetSymbolAddress((void**)&vl, g_vl);
    cudaGetSymbolAddress((void**)&aoh, g_aoh); cudaGetSymbolAddress((void**)&aol, g_aol);
    cudaGetSymbolAddress((void**)&wqh, g_wqh); cudaGetSymbolAddress((void**)&wql, g_wql);
    cudaGetSymbolAddress((void**)&wkh, g_wkh); cudaGetSymbolAddress((void**)&wkl, g_wkl);
    cudaGetSymbolAddress((void**)&wvh, g_wvh); cudaGetSymbolAddress((void**)&wvl, g_wvl);
    cudaGetSymbolAddress((void**)&woh, g_woh); cudaGetSymbolAddress((void**)&wol, g_wol);

    // ---- input conversions ----
    {
        int n4 = MROWS * DQ / 4;
        conv_split_kernel<<<(n4 + 255) / 256, 256>>>(x, xh, xl, n4);
        n4 = MROWS * DC / 4;
        conv_split_kernel<<<(n4 + 255) / 256, 256>>>(ctx, ch, cl, n4);
    }
    convT_kernel<<<dim3(INNER / 32, DQ / 32), dim3(32, 8)>>>(Wq, wqh, wql, DQ, INNER);
    convT_kernel<<<dim3(INNER / 32, DC / 32), dim3(32, 8)>>>(Wk, wkh, wkl, DC, INNER);
    convT_kernel<<<dim3(INNER / 32, DC / 32), dim3(32, 8)>>>(Wv, wvh, wvl, DC, INNER);
    convT_kernel<<<dim3(DQ / 32, INNER / 32), dim3(32, 8)>>>(Wo, woh, wol, INNER, DQ);

    // ---- projections -> bf16 hi/lo directly ----
    mma_gemm3_kernel<<<dim3(INNER / 128, MROWS / 128), 256>>>(
        xh, xl, wqh, wql, nullptr, nullptr, qh, ql, MROWS, INNER, DQ);
    mma_gemm3_kernel<<<dim3(INNER / 128, MROWS / 128), 256>>>(
        ch, cl, wkh, wkl, nullptr, nullptr, kh, kl, MROWS, INNER, DC);
    mma_gemm3_kernel<<<dim3(INNER / 128, MROWS / 128), 256>>>(
        ch, cl, wvh, wvl, nullptr, nullptr, vh, vl, MROWS, INNER, DC);

    // ---- tensor-core flash attention ----
    cudaFuncSetAttribute(flash_mma_kernel, cudaFuncAttributeMaxDynamicSharedMemorySize,
                         FLASH_SMEM);
    flash_mma_kernel<<<dim3(NQ / 128, NHEADS, BATCH), 256, FLASH_SMEM>>>(
        qh, ql, kh, kl, vh, vl, aoh, aol);

    // ---- output projection (fp32 + bias) ----
    mma_gemm3_kernel<<<dim3(DQ / 128, MROWS / 128), 256>>>(
        aoh, aol, woh, wol, bo, out, nullptr, nullptr, MROWS, DQ, INNER);
}